// round 2
// baseline (speedup 1.0000x reference)
// CrossLayerTranscoder — tf32 mma.sync GEMM (family-portable PTX; tcgen05 is
// unavailable because the harness targets plain sm_103).
//
// encode: feats[l] = relu(resid[l] @ enc_w[l]^T)            M=2048,N=512,K=2048
// decode: recon[t] = sum_{s<=t} feats[s] @ dec_w[s,t]^T     M=2048,N=2048,K=(t+1)*512
//
// CTA 128x128x32, 4-stage cp.async pipeline, 8 warps (4x2) of 32x64,
// m16n8k8 tf32 mma with cvt.rna rounding, XOR-swizzled SMEM (conflict-free
// STS via cp.async.128 and LDS.32 fragment reads).

#include <cuda_runtime.h>
#include <cstdint>
#include <cstddef>

#define L_DIM 16
#define BS_DIM 2048   // B*S
#define H_DIM 2048
#define F_DIM 512

#define TM 128
#define TN 128
#define TK 32
#define STAGES 4
#define NTHREADS 256

#define TILE_FLOATS (TM * TK)            // 4096 floats (16 KB) per A or B tile
#define STAGE_FLOATS (2 * TILE_FLOATS)   // 8192
#define SMEM_BYTES (STAGES * STAGE_FLOATS * 4)   // 131072
#define CHUNKS_PER_TILE (TM * 8)         // 1024 x 16B chunks per tile

__device__ __forceinline__ uint32_t smem_u32(const void* p) {
    uint32_t a;
    asm("{ .reg .u64 t; cvta.to.shared.u64 t, %1; cvt.u32.u64 %0, t; }" : "=r"(a) : "l"(p));
    return a;
}
__device__ __forceinline__ void cp_async16(uint32_t dst, const float* src) {
    asm volatile("cp.async.cg.shared.global [%0], [%1], 16;" :: "r"(dst), "l"(src));
}
__device__ __forceinline__ void cp_commit() { asm volatile("cp.async.commit_group;"); }
template <int N> __device__ __forceinline__ void cp_wait() {
    asm volatile("cp.async.wait_group %0;" :: "n"(N));
}
__device__ __forceinline__ uint32_t f2tf32(float x) {
    uint32_t r; asm("cvt.rna.tf32.f32 %0, %1;" : "=r"(r) : "f"(x)); return r;
}
__device__ __forceinline__ void mma_tf32(float* c, const uint32_t* a, const uint32_t* b) {
    asm volatile(
        "mma.sync.aligned.m16n8k8.row.col.f32.tf32.tf32.f32 "
        "{%0,%1,%2,%3}, {%4,%5,%6,%7}, {%8,%9}, {%0,%1,%2,%3};"
        : "+f"(c[0]), "+f"(c[1]), "+f"(c[2]), "+f"(c[3])
        : "r"(a[0]), "r"(a[1]), "r"(a[2]), "r"(a[3]), "r"(b[0]), "r"(b[1]));
}

// swizzled float index within one tile: 16B-chunk c XOR low row bits.
// conflict-free for cp.async row writes AND for the m16n8k8 fragment reads.
__device__ __forceinline__ int sidx(int row, int k) {
    return (((row << 3) + ((k >> 2) ^ (row & 7))) << 2) + (k & 3);
}

template <bool ENCODE>
__global__ __launch_bounds__(NTHREADS, 1)
void clt_gemm(const float* __restrict__ gA, const float* __restrict__ gB,
              float* __restrict__ gOut) {
    extern __shared__ float smem[];
    const int tid  = threadIdx.x;
    const int lane = tid & 31;
    const int w    = tid >> 5;
    const int wm   = w & 3;        // 4 warps along M
    const int wn   = w >> 2;       // 2 warps along N
    const int m0   = blockIdx.x * TM;
    const int n0   = blockIdx.y * TN;
    const int z    = blockIdx.z;
    const int iters = ENCODE ? (H_DIM / TK) : ((z + 1) * (F_DIM / TK));

    const uint32_t sbase = smem_u32(smem);

    float acc[2][8][4];
    #pragma unroll
    for (int mt = 0; mt < 2; mt++)
        #pragma unroll
        for (int nt = 0; nt < 8; nt++)
            #pragma unroll
            for (int r = 0; r < 4; r++) acc[mt][nt][r] = 0.0f;

    // ---- stage loader: 2048 x 16B chunks, 8 per thread ----
    auto load_stage = [&](int fi, int slot) {
        int kbase, lda, ldb;
        const float *Ab, *Bb;
        if (ENCODE) {
            kbase = fi * TK;
            Ab = gA + (size_t)z * BS_DIM * H_DIM;       // resid[z]
            Bb = gB + (size_t)z * F_DIM * H_DIM;        // enc_w[z]
            lda = H_DIM; ldb = H_DIM;
        } else {
            int s  = fi >> 4;                           // 16 chunks per source layer
            kbase  = (fi & 15) * TK;
            Ab = gA + (size_t)s * BS_DIM * F_DIM;       // feats[s]
            Bb = gB + ((size_t)s * L_DIM + z) * (size_t)H_DIM * F_DIM;  // dec_w[s][z]
            lda = F_DIM; ldb = F_DIM;
        }
        uint32_t sA = sbase + (uint32_t)slot * STAGE_FLOATS * 4;
        uint32_t sB = sA + TILE_FLOATS * 4;
        #pragma unroll
        for (int j = 0; j < 8; j++) {
            int q   = j * NTHREADS + tid;
            int isB = q >= CHUNKS_PER_TILE;
            int qq  = isB ? q - CHUNKS_PER_TILE : q;
            int row = qq >> 3;
            int c   = qq & 7;
            const float* src = (isB ? Bb + (size_t)(n0 + row) * ldb
                                    : Ab + (size_t)(m0 + row) * lda) + kbase + c * 4;
            uint32_t dst = (isB ? sB : sA) + ((((row << 3) + (c ^ (row & 7)))) << 4);
            cp_async16(dst, src);
        }
        cp_commit();
    };

    // ---- prologue: prefetch STAGES-1 stages ----
    int fetch = 0;
    #pragma unroll
    for (int s = 0; s < STAGES - 1; s++) { load_stage(fetch, fetch % STAGES); fetch++; }

    // ---- mainloop ----
    for (int i = 0; i < iters; i++) {
        cp_wait<STAGES - 2>();
        __syncthreads();
        if (fetch < iters) { load_stage(fetch, fetch % STAGES); fetch++; }

        const float* sA = smem + (size_t)(i % STAGES) * STAGE_FLOATS;
        const float* sB = sA + TILE_FLOATS;

        #pragma unroll
        for (int ks = 0; ks < 4; ks++) {
            const int kk = ks * 8 + (lane & 3);
            uint32_t af[2][4], bf[8][2];
            #pragma unroll
            for (int mt = 0; mt < 2; mt++) {
                int r = wm * 32 + mt * 16 + (lane >> 2);
                af[mt][0] = f2tf32(sA[sidx(r,     kk)]);
                af[mt][1] = f2tf32(sA[sidx(r + 8, kk)]);
                af[mt][2] = f2tf32(sA[sidx(r,     kk + 4)]);
                af[mt][3] = f2tf32(sA[sidx(r + 8, kk + 4)]);
            }
            #pragma unroll
            for (int nt = 0; nt < 8; nt++) {
                int n = wn * 64 + nt * 8 + (lane >> 2);
                bf[nt][0] = f2tf32(sB[sidx(n, kk)]);
                bf[nt][1] = f2tf32(sB[sidx(n, kk + 4)]);
            }
            #pragma unroll
            for (int mt = 0; mt < 2; mt++)
                #pragma unroll
                for (int nt = 0; nt < 8; nt++)
                    mma_tf32(acc[mt][nt], af[mt], bf[nt]);
        }
    }

    // ---- epilogue: direct float2 stores ----
    const int ldo = ENCODE ? F_DIM : H_DIM;
    float* ob = gOut + (size_t)z * BS_DIM * ldo;
    #pragma unroll
    for (int mt = 0; mt < 2; mt++) {
        #pragma unroll
        for (int nt = 0; nt < 8; nt++) {
            int row = m0 + wm * 32 + mt * 16 + (lane >> 2);
            int col = n0 + wn * 64 + nt * 8 + (lane & 3) * 2;
            float v0 = acc[mt][nt][0], v1 = acc[mt][nt][1];
            float v2 = acc[mt][nt][2], v3 = acc[mt][nt][3];
            if (ENCODE) {
                v0 = fmaxf(v0, 0.0f); v1 = fmaxf(v1, 0.0f);
                v2 = fmaxf(v2, 0.0f); v3 = fmaxf(v3, 0.0f);
            }
            float2 p0 = make_float2(v0, v1);
            float2 p1 = make_float2(v2, v3);
            *(float2*)&ob[(size_t)row * ldo + col]       = p0;
            *(float2*)&ob[(size_t)(row + 8) * ldo + col] = p1;
        }
    }
}

extern "C" void kernel_launch(void* const* d_in, const int* in_sizes, int n_in,
                              void* d_out, int out_size) {
    (void)in_sizes; (void)n_in; (void)out_size;
    const float* resid = (const float*)d_in[0];   // [L, B, S, H]
    const float* enc_w = (const float*)d_in[1];   // [L, F, H]
    const float* dec_w = (const float*)d_in[2];   // [L, L, H, F]
    float* out   = (float*)d_out;
    float* feats = out;                                   // [L, BS, F]
    float* recon = out + (size_t)L_DIM * BS_DIM * F_DIM;  // [L, BS, H]

    cudaFuncSetAttribute(clt_gemm<true>,  cudaFuncAttributeMaxDynamicSharedMemorySize, SMEM_BYTES);
    cudaFuncSetAttribute(clt_gemm<false>, cudaFuncAttributeMaxDynamicSharedMemorySize, SMEM_BYTES);

    dim3 grid_enc(BS_DIM / TM, F_DIM / TN, L_DIM);   // 16 x 4 x 16
    clt_gemm<true><<<grid_enc, NTHREADS, SMEM_BYTES>>>(resid, enc_w, feats);

    dim3 grid_dec(BS_DIM / TM, H_DIM / TN, L_DIM);   // 16 x 16 x 16
    clt_gemm<false><<<grid_dec, NTHREADS, SMEM_BYTES>>>(feats, dec_w, recon);
}